// round 1
// baseline (speedup 1.0000x reference)
#include <cuda_runtime.h>
#include <cuda_bf16.h>

#define N_NODES 100000
#define M_HYPER 50000
#define N_TOTAL 150000
#define D_IN 512
#define H_LAT 256
#define N_CLASS 40
#define NNZ 4800000

// ---------------- scratch (static device memory; no allocs allowed) ----------------
__device__ float g_bufA[(size_t)N_TOTAL * H_LAT];   // 153.6 MB
__device__ float g_bufB[(size_t)N_TOTAL * H_LAT];   // 153.6 MB
__device__ float g_acc [(size_t)N_TOTAL * H_LAT];   // 153.6 MB
__device__ int   g_counts[N_TOTAL];
__device__ int   g_row_ptr[N_TOTAL + 1];
__device__ int   g_row_fill[N_TOTAL];
__device__ int   g_bsum[256];
__device__ int   g_csr_col[NNZ];
__device__ float g_csr_val[NNZ];

// ---------------- GEMM: emb = X @ W_red + b_red  -> g_bufA and g_acc ----------------
#define BM 128
#define BN 128
#define BK 8

__global__ void gemm_red_kernel(const float* __restrict__ X,
                                const float* __restrict__ W,
                                const float* __restrict__ b) {
    __shared__ float As[BK][BM + 4];   // transposed: As[k][m], padded
    __shared__ float Bs[BK][BN];

    const int tid = threadIdx.x;
    const int tx = tid & 15;
    const int ty = tid >> 4;
    const int block_m = blockIdx.y * BM;
    const int block_n = blockIdx.x * BN;

    float acc[8][8];
#pragma unroll
    for (int i = 0; i < 8; i++)
#pragma unroll
        for (int j = 0; j < 8; j++) acc[i][j] = 0.f;

    const int a_row = tid >> 1;          // 0..127
    const int a_k   = (tid & 1) * 4;     // 0 or 4
    const int b_k   = tid >> 5;          // 0..7
    const int b_n   = (tid & 31) * 4;    // 0..124
    const int row_g = block_m + a_row;

    for (int k0 = 0; k0 < D_IN; k0 += BK) {
        float4 av = make_float4(0.f, 0.f, 0.f, 0.f);
        if (row_g < N_TOTAL)
            av = *(const float4*)(X + (size_t)row_g * D_IN + k0 + a_k);
        As[a_k + 0][a_row] = av.x;
        As[a_k + 1][a_row] = av.y;
        As[a_k + 2][a_row] = av.z;
        As[a_k + 3][a_row] = av.w;

        float4 bv = *(const float4*)(W + (size_t)(k0 + b_k) * H_LAT + block_n + b_n);
        *(float4*)&Bs[b_k][b_n] = bv;
        __syncthreads();

#pragma unroll
        for (int kk = 0; kk < BK; kk++) {
            float a_frag[8], b_frag[8];
            *(float4*)&a_frag[0] = *(const float4*)&As[kk][ty * 8];
            *(float4*)&a_frag[4] = *(const float4*)&As[kk][ty * 8 + 4];
            *(float4*)&b_frag[0] = *(const float4*)&Bs[kk][tx * 8];
            *(float4*)&b_frag[4] = *(const float4*)&Bs[kk][tx * 8 + 4];
#pragma unroll
            for (int i = 0; i < 8; i++)
#pragma unroll
                for (int j = 0; j < 8; j++)
                    acc[i][j] += a_frag[i] * b_frag[j];
        }
        __syncthreads();
    }

#pragma unroll
    for (int i = 0; i < 8; i++) {
        int r = block_m + ty * 8 + i;
        if (r < N_TOTAL) {
#pragma unroll
            for (int j = 0; j < 8; j += 4) {
                int c = block_n + tx * 8 + j;
                float4 v;
                v.x = acc[i][j + 0] + b[c + 0];
                v.y = acc[i][j + 1] + b[c + 1];
                v.z = acc[i][j + 2] + b[c + 2];
                v.w = acc[i][j + 3] + b[c + 3];
                size_t o = (size_t)r * H_LAT + c;
                *(float4*)(g_bufA + o) = v;
                *(float4*)(g_acc + o) = v;
            }
        }
    }
}

// ---------------- CSR build ----------------
__global__ void zero_counts_kernel() {
    int i = blockIdx.x * blockDim.x + threadIdx.x;
    if (i < N_TOTAL) g_counts[i] = 0;
}

__global__ void hist_kernel(const int* __restrict__ rows) {
    int i = blockIdx.x * blockDim.x + threadIdx.x;
    if (i < NNZ) atomicAdd(&g_counts[rows[i]], 1);
}

#define SCAN_CHUNK 1024
#define SCAN_NBLK ((N_TOTAL + SCAN_CHUNK - 1) / SCAN_CHUNK)   // 147

__global__ void scan_pass1_kernel() {
    __shared__ int sdata[8];
    int b = blockIdx.x, t = threadIdx.x;
    int base = b * SCAN_CHUNK;
    int s = 0;
#pragma unroll
    for (int j = 0; j < 4; j++) {
        int i = base + t * 4 + j;
        if (i < N_TOTAL) s += g_counts[i];
    }
#pragma unroll
    for (int o = 16; o; o >>= 1) s += __shfl_xor_sync(0xffffffffu, s, o);
    if ((t & 31) == 0) sdata[t >> 5] = s;
    __syncthreads();
    if (t == 0) {
        int tot = 0;
        for (int w = 0; w < 8; w++) tot += sdata[w];
        g_bsum[b] = tot;
    }
}

__global__ void scan_pass2_kernel() {
    if (threadIdx.x == 0) {
        int run = 0;
        for (int i = 0; i < SCAN_NBLK; i++) {
            int v = g_bsum[i];
            g_bsum[i] = run;
            run += v;
        }
        g_row_ptr[N_TOTAL] = run;   // == NNZ
    }
}

__global__ void scan_pass3_kernel() {
    __shared__ int warp_sums[8];
    int b = blockIdx.x, t = threadIdx.x;
    int base = b * SCAN_CHUNK;
    int vals[4];
#pragma unroll
    for (int j = 0; j < 4; j++) {
        int i = base + t * 4 + j;
        vals[j] = (i < N_TOTAL) ? g_counts[i] : 0;
    }
    int tsum = vals[0] + vals[1] + vals[2] + vals[3];
    int lane = t & 31, w = t >> 5;
    int x = tsum;
#pragma unroll
    for (int o = 1; o < 32; o <<= 1) {
        int y = __shfl_up_sync(0xffffffffu, x, o);
        if (lane >= o) x += y;
    }
    if (lane == 31) warp_sums[w] = x;
    __syncthreads();
    if (t == 0) {
        int run = 0;
        for (int i = 0; i < 8; i++) {
            int v = warp_sums[i];
            warp_sums[i] = run;
            run += v;
        }
    }
    __syncthreads();
    int run = (x - tsum) + warp_sums[w] + g_bsum[b];
#pragma unroll
    for (int j = 0; j < 4; j++) {
        int i = base + t * 4 + j;
        if (i < N_TOTAL) g_row_ptr[i] = run;
        run += vals[j];
    }
}

__global__ void copy_fill_kernel() {
    int i = blockIdx.x * blockDim.x + threadIdx.x;
    if (i < N_TOTAL) g_row_fill[i] = g_row_ptr[i];
}

__global__ void scatter_kernel(const float* __restrict__ evals,
                               const int* __restrict__ rows,
                               const int* __restrict__ cols) {
    int i = blockIdx.x * blockDim.x + threadIdx.x;
    if (i < NNZ) {
        int r = rows[i];
        int p = atomicAdd(&g_row_fill[r], 1);
        g_csr_col[p] = cols[i];
        g_csr_val[p] = evals[i];
    }
}

// ---------------- SpMM: next[r] = sum_e val[e]*cur[col[e]], acc += next ----------------
__global__ void spmm_kernel(int dir) {
    const float* __restrict__ cur = dir ? g_bufB : g_bufA;
    float* __restrict__ next      = dir ? g_bufA : g_bufB;

    int wg = (blockIdx.x * blockDim.x + threadIdx.x) >> 5;
    int lane = threadIdx.x & 31;
    if (wg >= N_TOTAL) return;

    int start = g_row_ptr[wg];
    int end   = g_row_ptr[wg + 1];

    float4 a0 = make_float4(0.f, 0.f, 0.f, 0.f);
    float4 a1 = make_float4(0.f, 0.f, 0.f, 0.f);

    int e = start;
    for (; e + 1 < end; e += 2) {
        int   c0 = g_csr_col[e],     c1 = g_csr_col[e + 1];
        float v0 = g_csr_val[e],     v1 = g_csr_val[e + 1];
        const float4* s0p = (const float4*)(cur + (size_t)c0 * H_LAT);
        const float4* s1p = (const float4*)(cur + (size_t)c1 * H_LAT);
        float4 x0 = s0p[lane];
        float4 y0 = s0p[lane + 32];
        float4 x1 = s1p[lane];
        float4 y1 = s1p[lane + 32];
        a0.x += v0 * x0.x; a0.y += v0 * x0.y; a0.z += v0 * x0.z; a0.w += v0 * x0.w;
        a1.x += v0 * y0.x; a1.y += v0 * y0.y; a1.z += v0 * y0.z; a1.w += v0 * y0.w;
        a0.x += v1 * x1.x; a0.y += v1 * x1.y; a0.z += v1 * x1.z; a0.w += v1 * x1.w;
        a1.x += v1 * y1.x; a1.y += v1 * y1.y; a1.z += v1 * y1.z; a1.w += v1 * y1.w;
    }
    if (e < end) {
        int   c0 = g_csr_col[e];
        float v0 = g_csr_val[e];
        const float4* s0p = (const float4*)(cur + (size_t)c0 * H_LAT);
        float4 x0 = s0p[lane];
        float4 y0 = s0p[lane + 32];
        a0.x += v0 * x0.x; a0.y += v0 * x0.y; a0.z += v0 * x0.z; a0.w += v0 * x0.w;
        a1.x += v0 * y0.x; a1.y += v0 * y0.y; a1.z += v0 * y0.z; a1.w += v0 * y0.w;
    }

    size_t o = (size_t)wg * H_LAT;
    ((float4*)(next + o))[lane]      = a0;
    ((float4*)(next + o))[lane + 32] = a1;

    float4* ap = (float4*)(g_acc + o);
    float4 t0 = ap[lane];
    float4 t1 = ap[lane + 32];
    t0.x += a0.x; t0.y += a0.y; t0.z += a0.z; t0.w += a0.w;
    t1.x += a1.x; t1.y += a1.y; t1.z += a1.z; t1.w += a1.w;
    ap[lane]      = t0;
    ap[lane + 32] = t1;
}

// ---------------- classifier: out = log_softmax((acc[:N]/4) @ W_cls + b_cls) ----------------
__global__ void classifier_kernel(const float* __restrict__ Wc,
                                  const float* __restrict__ bc,
                                  float* __restrict__ out) {
    __shared__ float Ws[H_LAT * N_CLASS];   // 40 KB
    __shared__ float rowbuf[4][H_LAT];      // 4 KB

    int tid = threadIdx.x;
    for (int i = tid; i < H_LAT * N_CLASS; i += 128) Ws[i] = Wc[i];
    __syncthreads();

    int warp = tid >> 5, lane = tid & 31;
    int r = blockIdx.x * 4 + warp;
    if (r >= N_NODES) return;

    const float* a = g_acc + (size_t)r * H_LAT;
#pragma unroll
    for (int j = 0; j < 2; j++) {
        float4 v = *(const float4*)(a + lane * 4 + j * 128);
        rowbuf[warp][lane * 4 + j * 128 + 0] = v.x * 0.25f;
        rowbuf[warp][lane * 4 + j * 128 + 1] = v.y * 0.25f;
        rowbuf[warp][lane * 4 + j * 128 + 2] = v.z * 0.25f;
        rowbuf[warp][lane * 4 + j * 128 + 3] = v.w * 0.25f;
    }
    __syncwarp();

    const bool has1 = (lane + 32) < N_CLASS;       // lanes 0..7
    const int  c1 = has1 ? (lane + 32) : 0;
    float z0 = bc[lane];
    float z1 = has1 ? bc[c1] : -3.0e38f;

    for (int k = 0; k < H_LAT; k++) {
        float v = rowbuf[warp][k];
        z0 += v * Ws[k * N_CLASS + lane];
        z1 += has1 ? v * Ws[k * N_CLASS + c1] : 0.f;
    }

    float m = fmaxf(z0, z1);
#pragma unroll
    for (int o = 16; o; o >>= 1) m = fmaxf(m, __shfl_xor_sync(0xffffffffu, m, o));
    float s = expf(z0 - m) + (has1 ? expf(z1 - m) : 0.f);
#pragma unroll
    for (int o = 16; o; o >>= 1) s += __shfl_xor_sync(0xffffffffu, s, o);
    float lse = m + logf(s);

    out[(size_t)r * N_CLASS + lane] = z0 - lse;
    if (has1) out[(size_t)r * N_CLASS + c1] = z1 - lse;
}

// ---------------- launch ----------------
extern "C" void kernel_launch(void* const* d_in, const int* in_sizes, int n_in,
                              void* d_out, int out_size) {
    const float* X         = (const float*)d_in[0];
    const float* W_red     = (const float*)d_in[1];
    const float* b_red     = (const float*)d_in[2];
    const float* W_cls     = (const float*)d_in[3];
    const float* b_cls     = (const float*)d_in[4];
    const float* edge_vals = (const float*)d_in[5];
    const int*   edge_rows = (const int*)d_in[6];
    const int*   edge_cols = (const int*)d_in[7];
    float* out = (float*)d_out;

    // GEMM: emb -> g_bufA, g_acc
    dim3 ggrid(H_LAT / BN, (N_TOTAL + BM - 1) / BM);
    gemm_red_kernel<<<ggrid, 256>>>(X, W_red, b_red);

    // CSR build
    zero_counts_kernel<<<(N_TOTAL + 255) / 256, 256>>>();
    hist_kernel<<<(NNZ + 255) / 256, 256>>>(edge_rows);
    scan_pass1_kernel<<<SCAN_NBLK, 256>>>();
    scan_pass2_kernel<<<1, 32>>>();
    scan_pass3_kernel<<<SCAN_NBLK, 256>>>();
    copy_fill_kernel<<<(N_TOTAL + 255) / 256, 256>>>();
    scatter_kernel<<<(NNZ + 255) / 256, 256>>>(edge_vals, edge_rows, edge_cols);

    // 3 SpMM layers (warp per row), acc += each
    int spmm_blocks = (N_TOTAL * 32 + 255) / 256;
    spmm_kernel<<<spmm_blocks, 256>>>(0);   // A -> B
    spmm_kernel<<<spmm_blocks, 256>>>(1);   // B -> A
    spmm_kernel<<<spmm_blocks, 256>>>(0);   // A -> B

    // classifier + log_softmax
    classifier_kernel<<<(N_NODES + 3) / 4, 128>>>(W_cls, b_cls, out);
}

// round 2
// speedup vs baseline: 1.5294x; 1.5294x over previous
#include <cuda_runtime.h>
#include <cuda_fp16.h>

#define N_NODES 100000
#define M_HYPER 50000
#define N_TOTAL 150000
#define D_IN 512
#define H_LAT 256
#define N_CLASS 40
#define NNZ 4800000

// ---------------- scratch (static device memory; no allocs allowed) ----------------
__device__ __half g_emb[(size_t)N_TOTAL * H_LAT];   // 76.8 MB
__device__ __half g_c1 [(size_t)N_TOTAL * H_LAT];   // 76.8 MB
__device__ __half g_c2 [(size_t)N_TOTAL * H_LAT];   // 76.8 MB
__device__ __half g_c3 [(size_t)N_NODES * H_LAT];   // 51.2 MB (only node rows)
__device__ int   g_counts[N_TOTAL];
__device__ int   g_row_ptr[N_TOTAL + 1];
__device__ int   g_row_fill[N_TOTAL];
__device__ int   g_bsum[256];
__device__ int2  g_csr_cv[NNZ];                     // {col, val-as-bits}

// ---------------- GEMM: emb = X @ W_red + b_red  -> g_emb (half) ----------------
#define BM 128
#define BN 128
#define BK 8

__global__ void gemm_red_kernel(const float* __restrict__ X,
                                const float* __restrict__ W,
                                const float* __restrict__ b) {
    __shared__ float As[BK][BM + 4];   // transposed: As[k][m], padded
    __shared__ float Bs[BK][BN];

    const int tid = threadIdx.x;
    const int tx = tid & 15;
    const int ty = tid >> 4;
    const int block_m = blockIdx.y * BM;
    const int block_n = blockIdx.x * BN;

    float acc[8][8];
#pragma unroll
    for (int i = 0; i < 8; i++)
#pragma unroll
        for (int j = 0; j < 8; j++) acc[i][j] = 0.f;

    const int a_row = tid >> 1;          // 0..127
    const int a_k   = (tid & 1) * 4;     // 0 or 4
    const int b_k   = tid >> 5;          // 0..7
    const int b_n   = (tid & 31) * 4;    // 0..124
    const int row_g = block_m + a_row;

    for (int k0 = 0; k0 < D_IN; k0 += BK) {
        float4 av = make_float4(0.f, 0.f, 0.f, 0.f);
        if (row_g < N_TOTAL)
            av = *(const float4*)(X + (size_t)row_g * D_IN + k0 + a_k);
        As[a_k + 0][a_row] = av.x;
        As[a_k + 1][a_row] = av.y;
        As[a_k + 2][a_row] = av.z;
        As[a_k + 3][a_row] = av.w;

        float4 bv = *(const float4*)(W + (size_t)(k0 + b_k) * H_LAT + block_n + b_n);
        *(float4*)&Bs[b_k][b_n] = bv;
        __syncthreads();

#pragma unroll
        for (int kk = 0; kk < BK; kk++) {
            float a_frag[8], b_frag[8];
            *(float4*)&a_frag[0] = *(const float4*)&As[kk][ty * 8];
            *(float4*)&a_frag[4] = *(const float4*)&As[kk][ty * 8 + 4];
            *(float4*)&b_frag[0] = *(const float4*)&Bs[kk][tx * 8];
            *(float4*)&b_frag[4] = *(const float4*)&Bs[kk][tx * 8 + 4];
#pragma unroll
            for (int i = 0; i < 8; i++)
#pragma unroll
                for (int j = 0; j < 8; j++)
                    acc[i][j] += a_frag[i] * b_frag[j];
        }
        __syncthreads();
    }

#pragma unroll
    for (int i = 0; i < 8; i++) {
        int r = block_m + ty * 8 + i;
        if (r < N_TOTAL) {
            int c0 = block_n + tx * 8;
            __half2 hv[4];
#pragma unroll
            for (int j = 0; j < 8; j += 2) {
                hv[j >> 1] = __floats2half2_rn(acc[i][j]     + b[c0 + j],
                                               acc[i][j + 1] + b[c0 + j + 1]);
            }
            *(uint4*)(g_emb + (size_t)r * H_LAT + c0) = *(uint4*)hv;
        }
    }
}

// ---------------- CSR build ----------------
__global__ void zero_counts_kernel() {
    int i = blockIdx.x * blockDim.x + threadIdx.x;
    if (i < N_TOTAL) g_counts[i] = 0;
}

__global__ void hist_kernel(const int* __restrict__ rows) {
    int i = blockIdx.x * blockDim.x + threadIdx.x;
    if (i < NNZ) atomicAdd(&g_counts[rows[i]], 1);
}

#define SCAN_CHUNK 1024
#define SCAN_NBLK ((N_TOTAL + SCAN_CHUNK - 1) / SCAN_CHUNK)   // 147

__global__ void scan_pass1_kernel() {
    __shared__ int sdata[8];
    int b = blockIdx.x, t = threadIdx.x;
    int base = b * SCAN_CHUNK;
    int s = 0;
#pragma unroll
    for (int j = 0; j < 4; j++) {
        int i = base + t * 4 + j;
        if (i < N_TOTAL) s += g_counts[i];
    }
#pragma unroll
    for (int o = 16; o; o >>= 1) s += __shfl_xor_sync(0xffffffffu, s, o);
    if ((t & 31) == 0) sdata[t >> 5] = s;
    __syncthreads();
    if (t == 0) {
        int tot = 0;
        for (int w = 0; w < 8; w++) tot += sdata[w];
        g_bsum[b] = tot;
    }
}

__global__ void scan_pass2_kernel() {
    if (threadIdx.x == 0) {
        int run = 0;
        for (int i = 0; i < SCAN_NBLK; i++) {
            int v = g_bsum[i];
            g_bsum[i] = run;
            run += v;
        }
        g_row_ptr[N_TOTAL] = run;   // == NNZ
    }
}

__global__ void scan_pass3_kernel() {
    __shared__ int warp_sums[8];
    int b = blockIdx.x, t = threadIdx.x;
    int base = b * SCAN_CHUNK;
    int vals[4];
#pragma unroll
    for (int j = 0; j < 4; j++) {
        int i = base + t * 4 + j;
        vals[j] = (i < N_TOTAL) ? g_counts[i] : 0;
    }
    int tsum = vals[0] + vals[1] + vals[2] + vals[3];
    int lane = t & 31, w = t >> 5;
    int x = tsum;
#pragma unroll
    for (int o = 1; o < 32; o <<= 1) {
        int y = __shfl_up_sync(0xffffffffu, x, o);
        if (lane >= o) x += y;
    }
    if (lane == 31) warp_sums[w] = x;
    __syncthreads();
    if (t == 0) {
        int run = 0;
        for (int i = 0; i < 8; i++) {
            int v = warp_sums[i];
            warp_sums[i] = run;
            run += v;
        }
    }
    __syncthreads();
    int run = (x - tsum) + warp_sums[w] + g_bsum[b];
#pragma unroll
    for (int j = 0; j < 4; j++) {
        int i = base + t * 4 + j;
        if (i < N_TOTAL) g_row_ptr[i] = run;
        run += vals[j];
    }
}

__global__ void copy_fill_kernel() {
    int i = blockIdx.x * blockDim.x + threadIdx.x;
    if (i < N_TOTAL) g_row_fill[i] = g_row_ptr[i];
}

__global__ void scatter_kernel(const float* __restrict__ evals,
                               const int* __restrict__ rows,
                               const int* __restrict__ cols) {
    int i = blockIdx.x * blockDim.x + threadIdx.x;
    if (i < NNZ) {
        int r = rows[i];
        int p = atomicAdd(&g_row_fill[r], 1);
        g_csr_cv[p] = make_int2(cols[i], __float_as_int(evals[i]));
    }
}

// ---------------- SpMM: next[r] = sum_e val[e]*cur[col[e]]   (half in, half out) ----------------
__device__ __forceinline__ void acc8(float* a, uint4 p, float v) {
    const __half2* h = (const __half2*)&p;
#pragma unroll
    for (int i = 0; i < 4; i++) {
        float2 f = __half22float2(h[i]);
        a[2 * i]     += v * f.x;
        a[2 * i + 1] += v * f.y;
    }
}

__global__ void spmm_half_kernel(const __half* __restrict__ cur,
                                 __half* __restrict__ next,
                                 int nrows) {
    int w = (blockIdx.x * blockDim.x + threadIdx.x) >> 5;
    int lane = threadIdx.x & 31;
    if (w >= nrows) return;

    int start = g_row_ptr[w];
    int end   = g_row_ptr[w + 1];

    float acc[8];
#pragma unroll
    for (int i = 0; i < 8; i++) acc[i] = 0.f;

    int e = start;
    for (; e + 1 < end; e += 2) {
        int2 cv0 = g_csr_cv[e];
        int2 cv1 = g_csr_cv[e + 1];
        uint4 p0 = ((const uint4*)(cur + (size_t)cv0.x * H_LAT))[lane];
        uint4 p1 = ((const uint4*)(cur + (size_t)cv1.x * H_LAT))[lane];
        acc8(acc, p0, __int_as_float(cv0.y));
        acc8(acc, p1, __int_as_float(cv1.y));
    }
    if (e < end) {
        int2 cv0 = g_csr_cv[e];
        uint4 p0 = ((const uint4*)(cur + (size_t)cv0.x * H_LAT))[lane];
        acc8(acc, p0, __int_as_float(cv0.y));
    }

    __half2 hv[4];
#pragma unroll
    for (int i = 0; i < 4; i++)
        hv[i] = __floats2half2_rn(acc[2 * i], acc[2 * i + 1]);
    ((uint4*)(next + (size_t)w * H_LAT))[lane] = *(uint4*)hv;
}

// ---------------- classifier: out = log_softmax(((emb+c1+c2+c3)/4) @ W_cls + b_cls) ----------------
__global__ void classifier_kernel(const float* __restrict__ Wc,
                                  const float* __restrict__ bc,
                                  float* __restrict__ out) {
    __shared__ float Ws[H_LAT * N_CLASS];   // 40 KB
    __shared__ float rowbuf[4][H_LAT];      // 4 KB

    int tid = threadIdx.x;
    for (int i = tid; i < H_LAT * N_CLASS; i += 128) Ws[i] = Wc[i];
    __syncthreads();

    int warp = tid >> 5, lane = tid & 31;
    int r = blockIdx.x * 4 + warp;
    if (r >= N_NODES) return;

    size_t o = (size_t)r * H_LAT;
    uint4 pe = ((const uint4*)(g_emb + o))[lane];
    uint4 p1 = ((const uint4*)(g_c1  + o))[lane];
    uint4 p2 = ((const uint4*)(g_c2  + o))[lane];
    uint4 p3 = ((const uint4*)(g_c3  + o))[lane];
    {
        const __half2* he = (const __half2*)&pe;
        const __half2* h1 = (const __half2*)&p1;
        const __half2* h2 = (const __half2*)&p2;
        const __half2* h3 = (const __half2*)&p3;
#pragma unroll
        for (int i = 0; i < 4; i++) {
            float2 fe = __half22float2(he[i]);
            float2 f1 = __half22float2(h1[i]);
            float2 f2 = __half22float2(h2[i]);
            float2 f3 = __half22float2(h3[i]);
            rowbuf[warp][lane * 8 + 2 * i]     = (fe.x + f1.x + f2.x + f3.x) * 0.25f;
            rowbuf[warp][lane * 8 + 2 * i + 1] = (fe.y + f1.y + f2.y + f3.y) * 0.25f;
        }
    }
    __syncwarp();

    const bool has1 = (lane + 32) < N_CLASS;       // lanes 0..7
    const int  c1 = has1 ? (lane + 32) : 0;
    float z0 = bc[lane];
    float z1 = has1 ? bc[c1] : -3.0e38f;

    for (int k = 0; k < H_LAT; k++) {
        float v = rowbuf[warp][k];
        z0 += v * Ws[k * N_CLASS + lane];
        z1 += has1 ? v * Ws[k * N_CLASS + c1] : 0.f;
    }

    float m = fmaxf(z0, z1);
#pragma unroll
    for (int o2 = 16; o2; o2 >>= 1) m = fmaxf(m, __shfl_xor_sync(0xffffffffu, m, o2));
    float s = expf(z0 - m) + (has1 ? expf(z1 - m) : 0.f);
#pragma unroll
    for (int o2 = 16; o2; o2 >>= 1) s += __shfl_xor_sync(0xffffffffu, s, o2);
    float lse = m + logf(s);

    out[(size_t)r * N_CLASS + lane] = z0 - lse;
    if (has1) out[(size_t)r * N_CLASS + c1] = z1 - lse;
}

// ---------------- launch ----------------
extern "C" void kernel_launch(void* const* d_in, const int* in_sizes, int n_in,
                              void* d_out, int out_size) {
    const float* X         = (const float*)d_in[0];
    const float* W_red     = (const float*)d_in[1];
    const float* b_red     = (const float*)d_in[2];
    const float* W_cls     = (const float*)d_in[3];
    const float* b_cls     = (const float*)d_in[4];
    const float* edge_vals = (const float*)d_in[5];
    const int*   edge_rows = (const int*)d_in[6];
    const int*   edge_cols = (const int*)d_in[7];
    float* out = (float*)d_out;

    // GEMM: emb -> g_emb (half)
    dim3 ggrid(H_LAT / BN, (N_TOTAL + BM - 1) / BM);
    gemm_red_kernel<<<ggrid, 256>>>(X, W_red, b_red);

    // CSR build
    zero_counts_kernel<<<(N_TOTAL + 255) / 256, 256>>>();
    hist_kernel<<<(NNZ + 255) / 256, 256>>>(edge_rows);
    scan_pass1_kernel<<<SCAN_NBLK, 256>>>();
    scan_pass2_kernel<<<1, 32>>>();
    scan_pass3_kernel<<<SCAN_NBLK, 256>>>();
    copy_fill_kernel<<<(N_TOTAL + 255) / 256, 256>>>();
    scatter_kernel<<<(NNZ + 255) / 256, 256>>>(edge_vals, edge_rows, edge_cols);

    // 3 SpMM layers (warp per row); layer 3 only needs node rows
    __half* d_emb; cudaGetSymbolAddress((void**)&d_emb, g_emb);
    __half* d_c1;  cudaGetSymbolAddress((void**)&d_c1,  g_c1);
    __half* d_c2;  cudaGetSymbolAddress((void**)&d_c2,  g_c2);
    __half* d_c3;  cudaGetSymbolAddress((void**)&d_c3,  g_c3);

    int blocks_full = (N_TOTAL * 32 + 255) / 256;
    int blocks_node = (N_NODES * 32 + 255) / 256;
    spmm_half_kernel<<<blocks_full, 256>>>(d_emb, d_c1, N_TOTAL);
    spmm_half_kernel<<<blocks_full, 256>>>(d_c1,  d_c2, N_TOTAL);
    spmm_half_kernel<<<blocks_node, 256>>>(d_c2,  d_c3, N_NODES);

    // classifier + log_softmax
    classifier_kernel<<<(N_NODES + 3) / 4, 128>>>(W_cls, b_cls, out);
}

// round 4
// speedup vs baseline: 2.2765x; 1.4885x over previous
#include <cuda_runtime.h>
#include <cuda_fp16.h>

#define N_NODES 100000
#define M_HYPER 50000
#define N_TOTAL 150000
#define D_IN 512
#define H_LAT 256
#define N_CLASS 40
#define NNZ 4800000

// ---------------- scratch (static device memory; no allocs allowed) ----------------
__device__ __half g_emb[(size_t)N_TOTAL * H_LAT];   // 76.8 MB
__device__ __half g_c1 [(size_t)N_TOTAL * H_LAT];   // 76.8 MB
__device__ __half g_c2 [(size_t)N_TOTAL * H_LAT];   // 76.8 MB
__device__ __half g_c3 [(size_t)N_NODES * H_LAT];   // 51.2 MB (only node rows)
__device__ int   g_counts[N_TOTAL];
__device__ int   g_row_ptr[N_TOTAL + 1];
__device__ int   g_row_fill[N_TOTAL];
__device__ int   g_bsum[256];
__device__ int2  g_csr_cv[NNZ];                     // {col, val-as-bits}

// ---------------- tf32 tensor-core GEMM: emb = X @ W_red + b_red -> g_emb (half) ----------------
#define GBM 128
#define GBN 128
#define GBK 32
#define ASTR 36      // padded floats per A row
#define BSTR 132     // padded floats per B row

__device__ __forceinline__ unsigned f2tf32(float x) {
    unsigned u;
    asm("cvt.rna.tf32.f32 %0, %1;" : "=r"(u) : "f"(x));
    return u;
}

__global__ __launch_bounds__(256, 2)
void gemm_tf32_kernel(const float* __restrict__ X,
                      const float* __restrict__ W,
                      const float* __restrict__ b) {
    __shared__ float As[GBM * ASTR];   // 18432 B
    __shared__ float Bs[GBK * BSTR];   // 16896 B

    const int tid = threadIdx.x;
    const int warp = tid >> 5;
    const int lane = tid & 31;
    const int qid  = lane >> 2;   // t/4
    const int qtid = lane & 3;    // t%4

    const int block_m = blockIdx.y * GBM;
    const int block_n = blockIdx.x * GBN;
    const int wm = (warp & 3) * 32;   // warp M offset in tile
    const int wn = (warp >> 2) * 64;  // warp N offset in tile

    // gmem load mapping
    const int a_r  = tid >> 3;        // 0..31 (rows, step 32)
    const int a_c4 = (tid & 7) * 4;   // col within 32
    const int b_k  = tid >> 5;        // 0..7 (k rows, step 8)
    const int b_c4 = (tid & 31) * 4;  // col within 128

    float acc[2][8][4];
#pragma unroll
    for (int i = 0; i < 2; i++)
#pragma unroll
        for (int j = 0; j < 8; j++)
#pragma unroll
            for (int k = 0; k < 4; k++) acc[i][j][k] = 0.f;

    float4 pa[4];
    float4 pb[4];

    // prefetch tile 0
#pragma unroll
    for (int i = 0; i < 4; i++) {
        int r = block_m + a_r + i * 32;
        pa[i] = (r < N_TOTAL) ? *(const float4*)(X + (size_t)r * D_IN + a_c4)
                              : make_float4(0.f, 0.f, 0.f, 0.f);
    }
#pragma unroll
    for (int i = 0; i < 4; i++) {
        int k = b_k + i * 8;
        pb[i] = *(const float4*)(W + (size_t)k * H_LAT + block_n + b_c4);
    }

    const int NKT = D_IN / GBK;   // 16
    for (int kt = 0; kt < NKT; kt++) {
        // store prefetched tile to smem (tf32-rounded)
#pragma unroll
        for (int i = 0; i < 4; i++) {
            float* dst = As + (a_r + i * 32) * ASTR + a_c4;
            dst[0] = __uint_as_float(f2tf32(pa[i].x));
            dst[1] = __uint_as_float(f2tf32(pa[i].y));
            dst[2] = __uint_as_float(f2tf32(pa[i].z));
            dst[3] = __uint_as_float(f2tf32(pa[i].w));
        }
#pragma unroll
        for (int i = 0; i < 4; i++) {
            float* dst = Bs + (b_k + i * 8) * BSTR + b_c4;
            dst[0] = __uint_as_float(f2tf32(pb[i].x));
            dst[1] = __uint_as_float(f2tf32(pb[i].y));
            dst[2] = __uint_as_float(f2tf32(pb[i].z));
            dst[3] = __uint_as_float(f2tf32(pb[i].w));
        }
        __syncthreads();

        // prefetch next tile while computing
        if (kt + 1 < NKT) {
            int k0n = (kt + 1) * GBK;
#pragma unroll
            for (int i = 0; i < 4; i++) {
                int r = block_m + a_r + i * 32;
                pa[i] = (r < N_TOTAL) ? *(const float4*)(X + (size_t)r * D_IN + k0n + a_c4)
                                      : make_float4(0.f, 0.f, 0.f, 0.f);
            }
#pragma unroll
            for (int i = 0; i < 4; i++) {
                int k = k0n + b_k + i * 8;
                pb[i] = *(const float4*)(W + (size_t)k * H_LAT + block_n + b_c4);
            }
        }

        // compute: 4 k-steps of 8
#pragma unroll
        for (int ks = 0; ks < 4; ks++) {
            const int k8 = ks * 8;
            unsigned af[2][4];
#pragma unroll
            for (int mt = 0; mt < 2; mt++) {
                const float* ab = As + (wm + mt * 16 + qid) * ASTR + k8 + qtid;
                af[mt][0] = __float_as_uint(ab[0]);
                af[mt][1] = __float_as_uint(ab[8 * ASTR]);
                af[mt][2] = __float_as_uint(ab[4]);
                af[mt][3] = __float_as_uint(ab[8 * ASTR + 4]);
            }
#pragma unroll
            for (int nt = 0; nt < 8; nt++) {
                const float* bb = Bs + (k8 + qtid) * BSTR + wn + nt * 8 + qid;
                unsigned b0 = __float_as_uint(bb[0]);
                unsigned b1 = __float_as_uint(bb[4 * BSTR]);
#pragma unroll
                for (int mt = 0; mt < 2; mt++) {
                    asm volatile(
                        "mma.sync.aligned.m16n8k8.row.col.f32.tf32.tf32.f32 "
                        "{%0,%1,%2,%3}, {%4,%5,%6,%7}, {%8,%9}, {%0,%1,%2,%3};"
                        : "+f"(acc[mt][nt][0]), "+f"(acc[mt][nt][1]),
                          "+f"(acc[mt][nt][2]), "+f"(acc[mt][nt][3])
                        : "r"(af[mt][0]), "r"(af[mt][1]), "r"(af[mt][2]), "r"(af[mt][3]),
                          "r"(b0), "r"(b1));
                }
            }
        }
        __syncthreads();
    }

    // epilogue: + bias, convert to half, store
#pragma unroll
    for (int mt = 0; mt < 2; mt++) {
        int r0 = block_m + wm + mt * 16 + qid;
#pragma unroll
        for (int nt = 0; nt < 8; nt++) {
            int c0 = block_n + wn + nt * 8 + qtid * 2;
            float bx = b[c0], by = b[c0 + 1];
            if (r0 < N_TOTAL) {
                __half2 h = __floats2half2_rn(acc[mt][nt][0] + bx, acc[mt][nt][1] + by);
                *(__half2*)(g_emb + (size_t)r0 * H_LAT + c0) = h;
            }
            if (r0 + 8 < N_TOTAL) {
                __half2 h = __floats2half2_rn(acc[mt][nt][2] + bx, acc[mt][nt][3] + by);
                *(__half2*)(g_emb + (size_t)(r0 + 8) * H_LAT + c0) = h;
            }
        }
    }
}

// ---------------- CSR build ----------------
__global__ void zero_counts_kernel() {
    int i = blockIdx.x * blockDim.x + threadIdx.x;
    if (i < N_TOTAL) g_counts[i] = 0;
}

__global__ void hist_kernel(const int* __restrict__ rows) {
    int i = blockIdx.x * blockDim.x + threadIdx.x;
    if (i < NNZ) atomicAdd(&g_counts[rows[i]], 1);
}

#define SCAN_CHUNK 1024
#define SCAN_NBLK ((N_TOTAL + SCAN_CHUNK - 1) / SCAN_CHUNK)   // 147

__global__ void scan_pass1_kernel() {
    __shared__ int sdata[8];
    int b = blockIdx.x, t = threadIdx.x;
    int base = b * SCAN_CHUNK;
    int s = 0;
#pragma unroll
    for (int j = 0; j < 4; j++) {
        int i = base + t * 4 + j;
        if (i < N_TOTAL) s += g_counts[i];
    }
#pragma unroll
    for (int o = 16; o; o >>= 1) s += __shfl_xor_sync(0xffffffffu, s, o);
    if ((t & 31) == 0) sdata[t >> 5] = s;
    __syncthreads();
    if (t == 0) {
        int tot = 0;
        for (int w = 0; w < 8; w++) tot += sdata[w];
        g_bsum[b] = tot;
    }
}

__global__ void scan_pass2_kernel() {
    if (threadIdx.x == 0) {
        int run = 0;
        for (int i = 0; i < SCAN_NBLK; i++) {
            int v = g_bsum[i];
            g_bsum[i] = run;
            run += v;
        }
        g_row_ptr[N_TOTAL] = run;   // == NNZ
    }
}

__global__ void scan_pass3_kernel() {
    __shared__ int warp_sums[8];
    int b = blockIdx.x, t = threadIdx.x;
    int base = b * SCAN_CHUNK;
    int vals[4];
#pragma unroll
    for (int j = 0; j < 4; j++) {
        int i = base + t * 4 + j;
        vals[j] = (i < N_TOTAL) ? g_counts[i] : 0;
    }
    int tsum = vals[0] + vals[1] + vals[2] + vals[3];
    int lane = t & 31, w = t >> 5;
    int x = tsum;
#pragma unroll
    for (int o = 1; o < 32; o <<= 1) {
        int y = __shfl_up_sync(0xffffffffu, x, o);
        if (lane >= o) x += y;
    }
    if (lane == 31) warp_sums[w] = x;
    __syncthreads();
    if (t == 0) {
        int run = 0;
        for (int i = 0; i < 8; i++) {
            int v = warp_sums[i];
            warp_sums[i] = run;
            run += v;
        }
    }
    __syncthreads();
    int run = (x - tsum) + warp_sums[w] + g_bsum[b];
#pragma unroll
    for (int j = 0; j < 4; j++) {
        int i = base + t * 4 + j;
        if (i < N_TOTAL) g_row_ptr[i] = run;
        run += vals[j];
    }
}

__global__ void copy_fill_kernel() {
    int i = blockIdx.x * blockDim.x + threadIdx.x;
    if (i < N_TOTAL) g_row_fill[i] = g_row_ptr[i];
}

__global__ void scatter_kernel(const float* __restrict__ evals,
                               const int* __restrict__ rows,
                               const int* __restrict__ cols) {
    int i = blockIdx.x * blockDim.x + threadIdx.x;
    if (i < NNZ) {
        int r = rows[i];
        int p = atomicAdd(&g_row_fill[r], 1);
        g_csr_cv[p] = make_int2(cols[i], __float_as_int(evals[i]));
    }
}

// ---------------- SpMM: next[r] = sum_e val[e]*cur[col[e]]   (half in, half out) ----------------
__device__ __forceinline__ void acc8(float* a, uint4 p, float v) {
    const __half2* h = (const __half2*)&p;
#pragma unroll
    for (int i = 0; i < 4; i++) {
        float2 f = __half22float2(h[i]);
        a[2 * i]     += v * f.x;
        a[2 * i + 1] += v * f.y;
    }
}

__global__ void spmm_half_kernel(const __half* __restrict__ cur,
                                 __half* __restrict__ next,
                                 int nrows) {
    int w = (blockIdx.x * blockDim.x + threadIdx.x) >> 5;
    int lane = threadIdx.x & 31;
    if (w >= nrows) return;

    int start = g_row_ptr[w];
    int end   = g_row_ptr[w + 1];

    float acc[8];
#pragma unroll
    for (int i = 0; i < 8; i++) acc[i] = 0.f;

    int e = start;
    for (; e + 1 < end; e += 2) {
        int2 cv0 = g_csr_cv[e];
        int2 cv1 = g_csr_cv[e + 1];
        uint4 p0 = ((const uint4*)(cur + (size_t)cv0.x * H_LAT))[lane];
        uint4 p1 = ((const uint4*)(cur + (size_t)cv1.x * H_LAT))[lane];
        acc8(acc, p0, __int_as_float(cv0.y));
        acc8(acc, p1, __int_as_float(cv1.y));
    }
    if (e < end) {
        int2 cv0 = g_csr_cv[e];
        uint4 p0 = ((const uint4*)(cur + (size_t)cv0.x * H_LAT))[lane];
        acc8(acc, p0, __int_as_float(cv0.y));
    }

    __half2 hv[4];
#pragma unroll
    for (int i = 0; i < 4; i++)
        hv[i] = __floats2half2_rn(acc[2 * i], acc[2 * i + 1]);
    ((uint4*)(next + (size_t)w * H_LAT))[lane] = *(uint4*)hv;
}

// ---------------- classifier: out = log_softmax(((emb+c1+c2+c3)/4) @ W_cls + b_cls) ----------------
__global__ void classifier_kernel(const float* __restrict__ Wc,
                                  const float* __restrict__ bc,
                                  float* __restrict__ out) {
    __shared__ float Ws[H_LAT * N_CLASS];   // 40 KB
    __shared__ float rowbuf[4][H_LAT];      // 4 KB

    int tid = threadIdx.x;
    for (int i = tid; i < H_LAT * N_CLASS; i += 128) Ws[i] = Wc[i];
    __syncthreads();

    int warp = tid >> 5, lane = tid & 31;
    int r = blockIdx.x * 4 + warp;
    if (r >= N_NODES) return;

    size_t o = (size_t)r * H_LAT;
    uint4 pe = ((const uint4*)(g_emb + o))[lane];
    uint4 p1 = ((const uint4*)(g_c1  + o))[lane];
    uint4 p2 = ((const uint4*)(g_c2  + o))[lane];
    uint4 p3 = ((const uint4*)(g_c3  + o))[lane];
    {
        const __half2* he = (const __half2*)&pe;
        const __half2* h1 = (const __half2*)&p1;
        const __half2* h2 = (const __half2*)&p2;
        const __half2* h3 = (const __half2*)&p3;
#pragma unroll
        for (int i = 0; i < 4; i++) {
            float2 fe = __half22float2(he[i]);
            float2 f1 = __half22float2(h1[i]);
            float2 f2 = __half22float2(h2[i]);
            float2 f3 = __half22float2(h3[i]);
            rowbuf[warp][lane * 8 + 2 * i]     = (fe.x + f1.x + f2.x + f3.x) * 0.25f;
            rowbuf[warp][lane * 8 + 2 * i + 1] = (fe.y + f1.y + f2.y + f3.y) * 0.25f;
        }
    }
    __syncwarp();

    const bool has1 = (lane + 32) < N_CLASS;       // lanes 0..7
    const int  c1 = has1 ? (lane + 32) : 0;
    float z0 = bc[lane];
    float z1 = has1 ? bc[c1] : -3.0e38f;

    for (int k = 0; k < H_LAT; k++) {
        float v = rowbuf[warp][k];
        z0 += v * Ws[k * N_CLASS + lane];
        z1 += has1 ? v * Ws[k * N_CLASS + c1] : 0.f;
    }

    float m = fmaxf(z0, z1);
#pragma unroll
    for (int o2 = 16; o2; o2 >>= 1) m = fmaxf(m, __shfl_xor_sync(0xffffffffu, m, o2));
    float s = expf(z0 - m) + (has1 ? expf(z1 - m) : 0.f);
#pragma unroll
    for (int o2 = 16; o2; o2 >>= 1) s += __shfl_xor_sync(0xffffffffu, s, o2);
    float lse = m + logf(s);

    out[(size_t)r * N_CLASS + lane] = z0 - lse;
    if (has1) out[(size_t)r * N_CLASS + c1] = z1 - lse;
}

// ---------------- launch ----------------
extern "C" void kernel_launch(void* const* d_in, const int* in_sizes, int n_in,
                              void* d_out, int out_size) {
    const float* X         = (const float*)d_in[0];
    const float* W_red     = (const float*)d_in[1];
    const float* b_red     = (const float*)d_in[2];
    const float* W_cls     = (const float*)d_in[3];
    const float* b_cls     = (const float*)d_in[4];
    const float* edge_vals = (const float*)d_in[5];
    const int*   edge_rows = (const int*)d_in[6];
    const int*   edge_cols = (const int*)d_in[7];
    float* out = (float*)d_out;

    // GEMM (tf32 tensor cores): emb -> g_emb (half)
    dim3 ggrid(H_LAT / GBN, (N_TOTAL + GBM - 1) / GBM);
    gemm_tf32_kernel<<<ggrid, 256>>>(X, W_red, b_red);

    // CSR build
    zero_counts_kernel<<<(N_TOTAL + 255) / 256, 256>>>();
    hist_kernel<<<(NNZ + 255) / 256, 256>>>(edge_rows);
    scan_pass1_kernel<<<SCAN_NBLK, 256>>>();
    scan_pass2_kernel<<<1, 32>>>();
    scan_pass3_kernel<<<SCAN_NBLK, 256>>>();
    copy_fill_kernel<<<(N_TOTAL + 255) / 256, 256>>>();
    scatter_kernel<<<(NNZ + 255) / 256, 256>>>(edge_vals, edge_rows, edge_cols);

    // 3 SpMM layers (warp per row); layer 3 only needs node rows
    __half* d_emb; cudaGetSymbolAddress((void**)&d_emb, g_emb);
    __half* d_c1;  cudaGetSymbolAddress((void**)&d_c1,  g_c1);
    __half* d_c2;  cudaGetSymbolAddress((void**)&d_c2,  g_c2);
    __half* d_c3;  cudaGetSymbolAddress((void**)&d_c3,  g_c3);

    int blocks_full = (N_TOTAL * 32 + 255) / 256;
    int blocks_node = (N_NODES * 32 + 255) / 256;
    spmm_half_kernel<<<blocks_full, 256>>>(d_emb, d_c1, N_TOTAL);
    spmm_half_kernel<<<blocks_full, 256>>>(d_c1,  d_c2, N_TOTAL);
    spmm_half_kernel<<<blocks_node, 256>>>(d_c2,  d_c3, N_NODES);

    // classifier + log_softmax
    classifier_kernel<<<(N_NODES + 3) / 4, 128>>>(W_cls, b_cls, out);
}

// round 9
// speedup vs baseline: 2.4130x; 1.0600x over previous
#include <cuda_runtime.h>
#include <cuda_fp16.h>

#define N_NODES 100000
#define M_HYPER 50000
#define N_TOTAL 150000
#define D_IN 512
#define H_LAT 256
#define N_CLASS 40
#define NNZ 4800000

// ---------------- scratch (static device memory; no allocs allowed) ----------------
__device__ __half g_emb[(size_t)N_TOTAL * H_LAT];   // 76.8 MB
__device__ __half g_c1 [(size_t)N_TOTAL * H_LAT];   // 76.8 MB
__device__ __half g_c2 [(size_t)N_TOTAL * H_LAT];   // 76.8 MB
__device__ __half g_c3 [(size_t)N_NODES * H_LAT];   // 51.2 MB (only node rows)
__device__ int   g_counts[N_TOTAL];
__device__ int   g_row_ptr[N_TOTAL + 1];
__device__ int   g_row_fill[N_TOTAL];
__device__ int   g_bsum[256];
__device__ int2  g_csr_cv[NNZ];                     // {col, val-as-bits}

// ---------------- tf32 tensor-core GEMM: emb = X @ W_red + b_red -> g_emb (half) ----------------
#define GBM 128
#define GBN 128
#define GBK 32
#define ASTR 36      // padded floats per A row
#define BSTR 132     // padded floats per B row

__device__ __forceinline__ unsigned f2tf32(float x) {
    unsigned u;
    asm("cvt.rna.tf32.f32 %0, %1;" : "=r"(u) : "f"(x));
    return u;
}

__global__ __launch_bounds__(256, 2)
void gemm_tf32_kernel(const float* __restrict__ X,
                      const float* __restrict__ W,
                      const float* __restrict__ b) {
    __shared__ float As[GBM * ASTR];   // 18432 B
    __shared__ float Bs[GBK * BSTR];   // 16896 B

    const int tid = threadIdx.x;
    const int warp = tid >> 5;
    const int lane = tid & 31;
    const int qid  = lane >> 2;   // t/4
    const int qtid = lane & 3;    // t%4

    const int block_m = blockIdx.y * GBM;
    const int block_n = blockIdx.x * GBN;
    const int wm = (warp & 3) * 32;   // warp M offset in tile
    const int wn = (warp >> 2) * 64;  // warp N offset in tile

    // gmem load mapping
    const int a_r  = tid >> 3;        // 0..31 (rows, step 32)
    const int a_c4 = (tid & 7) * 4;   // col within 32
    const int b_k  = tid >> 5;        // 0..7 (k rows, step 8)
    const int b_c4 = (tid & 31) * 4;  // col within 128

    float acc[2][8][4];
#pragma unroll
    for (int i = 0; i < 2; i++)
#pragma unroll
        for (int j = 0; j < 8; j++)
#pragma unroll
            for (int k = 0; k < 4; k++) acc[i][j][k] = 0.f;

    float4 pa[4];
    float4 pb[4];

    // prefetch tile 0
#pragma unroll
    for (int i = 0; i < 4; i++) {
        int r = block_m + a_r + i * 32;
        pa[i] = (r < N_TOTAL) ? *(const float4*)(X + (size_t)r * D_IN + a_c4)
                              : make_float4(0.f, 0.f, 0.f, 0.f);
    }
#pragma unroll
    for (int i = 0; i < 4; i++) {
        int k = b_k + i * 8;
        pb[i] = *(const float4*)(W + (size_t)k * H_LAT + block_n + b_c4);
    }

    const int NKT = D_IN / GBK;   // 16
    for (int kt = 0; kt < NKT; kt++) {
        // store prefetched tile to smem (tf32-rounded)
#pragma unroll
        for (int i = 0; i < 4; i++) {
            float* dst = As + (a_r + i * 32) * ASTR + a_c4;
            dst[0] = __uint_as_float(f2tf32(pa[i].x));
            dst[1] = __uint_as_float(f2tf32(pa[i].y));
            dst[2] = __uint_as_float(f2tf32(pa[i].z));
            dst[3] = __uint_as_float(f2tf32(pa[i].w));
        }
#pragma unroll
        for (int i = 0; i < 4; i++) {
            float* dst = Bs + (b_k + i * 8) * BSTR + b_c4;
            dst[0] = __uint_as_float(f2tf32(pb[i].x));
            dst[1] = __uint_as_float(f2tf32(pb[i].y));
            dst[2] = __uint_as_float(f2tf32(pb[i].z));
            dst[3] = __uint_as_float(f2tf32(pb[i].w));
        }
        __syncthreads();

        // prefetch next tile while computing
        if (kt + 1 < NKT) {
            int k0n = (kt + 1) * GBK;
#pragma unroll
            for (int i = 0; i < 4; i++) {
                int r = block_m + a_r + i * 32;
                pa[i] = (r < N_TOTAL) ? *(const float4*)(X + (size_t)r * D_IN + k0n + a_c4)
                                      : make_float4(0.f, 0.f, 0.f, 0.f);
            }
#pragma unroll
            for (int i = 0; i < 4; i++) {
                int k = k0n + b_k + i * 8;
                pb[i] = *(const float4*)(W + (size_t)k * H_LAT + block_n + b_c4);
            }
        }

        // compute: 4 k-steps of 8
#pragma unroll
        for (int ks = 0; ks < 4; ks++) {
            const int k8 = ks * 8;
            unsigned af[2][4];
#pragma unroll
            for (int mt = 0; mt < 2; mt++) {
                const float* ab = As + (wm + mt * 16 + qid) * ASTR + k8 + qtid;
                af[mt][0] = __float_as_uint(ab[0]);
                af[mt][1] = __float_as_uint(ab[8 * ASTR]);
                af[mt][2] = __float_as_uint(ab[4]);
                af[mt][3] = __float_as_uint(ab[8 * ASTR + 4]);
            }
#pragma unroll
            for (int nt = 0; nt < 8; nt++) {
                const float* bb = Bs + (k8 + qtid) * BSTR + wn + nt * 8 + qid;
                unsigned b0 = __float_as_uint(bb[0]);
                unsigned b1 = __float_as_uint(bb[4 * BSTR]);
#pragma unroll
                for (int mt = 0; mt < 2; mt++) {
                    asm volatile(
                        "mma.sync.aligned.m16n8k8.row.col.f32.tf32.tf32.f32 "
                        "{%0,%1,%2,%3}, {%4,%5,%6,%7}, {%8,%9}, {%0,%1,%2,%3};"
                        : "+f"(acc[mt][nt][0]), "+f"(acc[mt][nt][1]),
                          "+f"(acc[mt][nt][2]), "+f"(acc[mt][nt][3])
                        : "r"(af[mt][0]), "r"(af[mt][1]), "r"(af[mt][2]), "r"(af[mt][3]),
                          "r"(b0), "r"(b1));
                }
            }
        }
        __syncthreads();
    }

    // epilogue: + bias, convert to half, store
#pragma unroll
    for (int mt = 0; mt < 2; mt++) {
        int r0 = block_m + wm + mt * 16 + qid;
#pragma unroll
        for (int nt = 0; nt < 8; nt++) {
            int c0 = block_n + wn + nt * 8 + qtid * 2;
            float bx = b[c0], by = b[c0 + 1];
            if (r0 < N_TOTAL) {
                __half2 h = __floats2half2_rn(acc[mt][nt][0] + bx, acc[mt][nt][1] + by);
                *(__half2*)(g_emb + (size_t)r0 * H_LAT + c0) = h;
            }
            if (r0 + 8 < N_TOTAL) {
                __half2 h = __floats2half2_rn(acc[mt][nt][2] + bx, acc[mt][nt][3] + by);
                *(__half2*)(g_emb + (size_t)(r0 + 8) * H_LAT + c0) = h;
            }
        }
    }
}

// ---------------- CSR build ----------------
__global__ void zero_counts_kernel() {
    int i = blockIdx.x * blockDim.x + threadIdx.x;
    if (i < N_TOTAL) g_counts[i] = 0;
}

// 4 edges per thread via int4
__global__ void hist_kernel(const int* __restrict__ rows) {
    int i = blockIdx.x * blockDim.x + threadIdx.x;
    int base = i * 4;
    if (base + 3 < NNZ) {
        int4 r4 = *(const int4*)(rows + base);
        atomicAdd(&g_counts[r4.x], 1);
        atomicAdd(&g_counts[r4.y], 1);
        atomicAdd(&g_counts[r4.z], 1);
        atomicAdd(&g_counts[r4.w], 1);
    } else {
        for (int j = base; j < NNZ; j++) atomicAdd(&g_counts[rows[j]], 1);
    }
}

#define SCAN_CHUNK 1024
#define SCAN_NBLK ((N_TOTAL + SCAN_CHUNK - 1) / SCAN_CHUNK)   // 147

__global__ void scan_pass1_kernel() {
    __shared__ int sdata[8];
    int b = blockIdx.x, t = threadIdx.x;
    int base = b * SCAN_CHUNK;
    int s = 0;
#pragma unroll
    for (int j = 0; j < 4; j++) {
        int i = base + t * 4 + j;
        if (i < N_TOTAL) s += g_counts[i];
    }
#pragma unroll
    for (int o = 16; o; o >>= 1) s += __shfl_xor_sync(0xffffffffu, s, o);
    if ((t & 31) == 0) sdata[t >> 5] = s;
    __syncthreads();
    if (t == 0) {
        int tot = 0;
        for (int w = 0; w < 8; w++) tot += sdata[w];
        g_bsum[b] = tot;
    }
}

__global__ void scan_pass2_kernel() {
    if (threadIdx.x == 0) {
        int run = 0;
        for (int i = 0; i < SCAN_NBLK; i++) {
            int v = g_bsum[i];
            g_bsum[i] = run;
            run += v;
        }
        g_row_ptr[N_TOTAL] = run;   // == NNZ
    }
}

// also writes g_row_fill (fused copy_fill)
__global__ void scan_pass3_kernel() {
    __shared__ int warp_sums[8];
    int b = blockIdx.x, t = threadIdx.x;
    int base = b * SCAN_CHUNK;
    int vals[4];
#pragma unroll
    for (int j = 0; j < 4; j++) {
        int i = base + t * 4 + j;
        vals[j] = (i < N_TOTAL) ? g_counts[i] : 0;
    }
    int tsum = vals[0] + vals[1] + vals[2] + vals[3];
    int lane = t & 31, w = t >> 5;
    int x = tsum;
#pragma unroll
    for (int o = 1; o < 32; o <<= 1) {
        int y = __shfl_up_sync(0xffffffffu, x, o);
        if (lane >= o) x += y;
    }
    if (lane == 31) warp_sums[w] = x;
    __syncthreads();
    if (t == 0) {
        int run = 0;
        for (int i = 0; i < 8; i++) {
            int v = warp_sums[i];
            warp_sums[i] = run;
            run += v;
        }
    }
    __syncthreads();
    int run = (x - tsum) + warp_sums[w] + g_bsum[b];
#pragma unroll
    for (int j = 0; j < 4; j++) {
        int i = base + t * 4 + j;
        if (i < N_TOTAL) {
            g_row_ptr[i]  = run;
            g_row_fill[i] = run;
        }
        run += vals[j];
    }
}

// 4 edges per thread via int4/float4
__global__ void scatter_kernel(const float* __restrict__ evals,
                               const int* __restrict__ rows,
                               const int* __restrict__ cols) {
    int i = blockIdx.x * blockDim.x + threadIdx.x;
    int base = i * 4;
    if (base + 3 < NNZ) {
        int4   r4 = *(const int4*)(rows + base);
        int4   c4 = *(const int4*)(cols + base);
        float4 v4 = *(const float4*)(evals + base);
        int p;
        p = atomicAdd(&g_row_fill[r4.x], 1); g_csr_cv[p] = make_int2(c4.x, __float_as_int(v4.x));
        p = atomicAdd(&g_row_fill[r4.y], 1); g_csr_cv[p] = make_int2(c4.y, __float_as_int(v4.y));
        p = atomicAdd(&g_row_fill[r4.z], 1); g_csr_cv[p] = make_int2(c4.z, __float_as_int(v4.z));
        p = atomicAdd(&g_row_fill[r4.w], 1); g_csr_cv[p] = make_int2(c4.w, __float_as_int(v4.w));
    } else {
        for (int j = base; j < NNZ; j++) {
            int r = rows[j];
            int p = atomicAdd(&g_row_fill[r], 1);
            g_csr_cv[p] = make_int2(cols[j], __float_as_int(evals[j]));
        }
    }
}

// ---------------- SpMM: next[r] = sum_e val[e]*cur[col[e]]   (half in, half out) ----------------
__device__ __forceinline__ void acc8(float* a, uint4 p, float v) {
    const __half2* h = (const __half2*)&p;
#pragma unroll
    for (int i = 0; i < 4; i++) {
        float2 f = __half22float2(h[i]);
        a[2 * i]     += v * f.x;
        a[2 * i + 1] += v * f.y;
    }
}

__global__ __launch_bounds__(256)
void spmm_half_kernel(const __half* __restrict__ cur,
                      __half* __restrict__ next,
                      int nrows) {
    int w = (blockIdx.x * blockDim.x + threadIdx.x) >> 5;
    int lane = threadIdx.x & 31;
    if (w >= nrows) return;

    int start = g_row_ptr[w];
    int end   = g_row_ptr[w + 1];

    float acc[8];
#pragma unroll
    for (int i = 0; i < 8; i++) acc[i] = 0.f;

    int e = start;
    int n4 = start + ((end - start) & ~3);
    for (; e < n4; e += 4) {
        int2 cv0 = g_csr_cv[e];
        int2 cv1 = g_csr_cv[e + 1];
        int2 cv2 = g_csr_cv[e + 2];
        int2 cv3 = g_csr_cv[e + 3];
        uint4 p0 = ((const uint4*)(cur + (size_t)cv0.x * H_LAT))[lane];
        uint4 p1 = ((const uint4*)(cur + (size_t)cv1.x * H_LAT))[lane];
        uint4 p2 = ((const uint4*)(cur + (size_t)cv2.x * H_LAT))[lane];
        uint4 p3 = ((const uint4*)(cur + (size_t)cv3.x * H_LAT))[lane];
        acc8(acc, p0, __int_as_float(cv0.y));
        acc8(acc, p1, __int_as_float(cv1.y));
        acc8(acc, p2, __int_as_float(cv2.y));
        acc8(acc, p3, __int_as_float(cv3.y));
    }
    for (; e < end; e++) {
        int2 cv0 = g_csr_cv[e];
        uint4 p0 = ((const uint4*)(cur + (size_t)cv0.x * H_LAT))[lane];
        acc8(acc, p0, __int_as_float(cv0.y));
    }

    __half2 hv[4];
#pragma unroll
    for (int i = 0; i < 4; i++)
        hv[i] = __floats2half2_rn(acc[2 * i], acc[2 * i + 1]);
    ((uint4*)(next + (size_t)w * H_LAT))[lane] = *(uint4*)hv;
}

// ---------------- classifier: out = log_softmax(((emb+c1+c2+c3)/4) @ W_cls + b_cls) ----------------
__global__ void classifier_kernel(const float* __restrict__ Wc,
                                  const float* __restrict__ bc,
                                  float* __restrict__ out) {
    __shared__ float Ws[H_LAT * N_CLASS];   // 40 KB
    __shared__ float rowbuf[4][H_LAT];      // 4 KB

    int tid = threadIdx.x;
    for (int i = tid; i < H_LAT * N_CLASS; i += 128) Ws[i] = Wc[i];
    __syncthreads();

    int warp = tid >> 5, lane = tid & 31;
    int r = blockIdx.x * 4 + warp;
    if (r >= N_NODES) return;

    size_t o = (size_t)r * H_LAT;
    uint4 pe = ((const uint4*)(g_emb + o))[lane];
    uint4 p1 = ((const uint4*)(g_c1  + o))[lane];
    uint4 p2 = ((const uint4*)(g_c2  + o))[lane];
    uint4 p3 = ((const uint4*)(g_c3  + o))[lane];
    {
        const __half2* he = (const __half2*)&pe;
        const __half2* h1 = (const __half2*)&p1;
        const __half2* h2 = (const __half2*)&p2;
        const __half2* h3 = (const __half2*)&p3;
#pragma unroll
        for (int i = 0; i < 4; i++) {
            float2 fe = __half22float2(he[i]);
            float2 f1 = __half22float2(h1[i]);
            float2 f2 = __half22float2(h2[i]);
            float2 f3 = __half22float2(h3[i]);
            rowbuf[warp][lane * 8 + 2 * i]     = (fe.x + f1.x + f2.x + f3.x) * 0.25f;
            rowbuf[warp][lane * 8 + 2 * i + 1] = (fe.y + f1.y + f2.y + f3.y) * 0.25f;
        }
    }
    __syncwarp();

    const bool has1 = (lane + 32) < N_CLASS;       // lanes 0..7
    const int  c1 = has1 ? (lane + 32) : 0;
    float z0 = bc[lane];
    float z1 = has1 ? bc[c1] : -3.0e38f;

    for (int k = 0; k < H_LAT; k++) {
        float v = rowbuf[warp][k];
        z0 += v * Ws[k * N_CLASS + lane];
        z1 += has1 ? v * Ws[k * N_CLASS + c1] : 0.f;
    }

    float m = fmaxf(z0, z1);
#pragma unroll
    for (int o2 = 16; o2; o2 >>= 1) m = fmaxf(m, __shfl_xor_sync(0xffffffffu, m, o2));
    float s = expf(z0 - m) + (has1 ? expf(z1 - m) : 0.f);
#pragma unroll
    for (int o2 = 16; o2; o2 >>= 1) s += __shfl_xor_sync(0xffffffffu, s, o2);
    float lse = m + logf(s);

    out[(size_t)r * N_CLASS + lane] = z0 - lse;
    if (has1) out[(size_t)r * N_CLASS + c1] = z1 - lse;
}

// ---------------- launch ----------------
extern "C" void kernel_launch(void* const* d_in, const int* in_sizes, int n_in,
                              void* d_out, int out_size) {
    const float* X         = (const float*)d_in[0];
    const float* W_red     = (const float*)d_in[1];
    const float* b_red     = (const float*)d_in[2];
    const float* W_cls     = (const float*)d_in[3];
    const float* b_cls     = (const float*)d_in[4];
    const float* edge_vals = (const float*)d_in[5];
    const int*   edge_rows = (const int*)d_in[6];
    const int*   edge_cols = (const int*)d_in[7];
    float* out = (float*)d_out;

    // one-time host resources (created on the pre-capture correctness call;
    // identical launch sequence every call — work is deterministic)
    static cudaStream_t s_side = nullptr;
    static cudaEvent_t  ev_fork = nullptr, ev_join = nullptr;
    if (s_side == nullptr) {
        cudaStreamCreateWithFlags(&s_side, cudaStreamNonBlocking);
        cudaEventCreateWithFlags(&ev_fork, cudaEventDisableTiming);
        cudaEventCreateWithFlags(&ev_join, cudaEventDisableTiming);
    }

    // fork: CSR build runs on side stream concurrent with GEMM on main stream
    cudaEventRecord(ev_fork, 0);
    cudaStreamWaitEvent(s_side, ev_fork, 0);

    // main stream: GEMM (tf32 tensor cores): emb -> g_emb (half)
    dim3 ggrid(H_LAT / GBN, (N_TOTAL + GBM - 1) / GBM);
    gemm_tf32_kernel<<<ggrid, 256>>>(X, W_red, b_red);

    // side stream: CSR build
    zero_counts_kernel<<<(N_TOTAL + 255) / 256, 256, 0, s_side>>>();
    hist_kernel<<<(NNZ / 4 + 255) / 256, 256, 0, s_side>>>(edge_rows);
    scan_pass1_kernel<<<SCAN_NBLK, 256, 0, s_side>>>();
    scan_pass2_kernel<<<1, 32, 0, s_side>>>();
    scan_pass3_kernel<<<SCAN_NBLK, 256, 0, s_side>>>();
    scatter_kernel<<<(NNZ / 4 + 255) / 256, 256, 0, s_side>>>(edge_vals, edge_rows, edge_cols);

    // join
    cudaEventRecord(ev_join, s_side);
    cudaStreamWaitEvent(0, ev_join, 0);

    // 3 SpMM layers (warp per row); layer 3 only needs node rows
    __half* d_emb; cudaGetSymbolAddress((void**)&d_emb, g_emb);
    __half* d_c1;  cudaGetSymbolAddress((void**)&d_c1,  g_c1);
    __half* d_c2;  cudaGetSymbolAddress((void**)&d_c2,  g_c2);
    __half* d_c3;  cudaGetSymbolAddress((void**)&d_c3,  g_c3);

    int blocks_full = (N_TOTAL * 32 + 255) / 256;
    int blocks_node = (N_NODES * 32 + 255) / 256;
    spmm_half_kernel<<<blocks_full, 256>>>(d_emb, d_c1, N_TOTAL);
    spmm_half_kernel<<<blocks_full, 256>>>(d_c1,  d_c2, N_TOTAL);
    spmm_half_kernel<<<blocks_node, 256>>>(d_c2,  d_c3, N_NODES);

    // classifier + log_softmax
    classifier_kernel<<<(N_NODES + 3) / 4, 128>>>(W_cls, b_cls, out);
}

// round 10
// speedup vs baseline: 2.6718x; 1.1073x over previous
#include <cuda_runtime.h>
#include <cuda_fp16.h>

#define N_NODES 100000
#define M_HYPER 50000
#define N_TOTAL 150000
#define D_IN 512
#define H_LAT 256
#define N_CLASS 40
#define NNZ 4800000

// ---------------- scratch (static device memory; no allocs allowed) ----------------
__device__ __half g_emb[(size_t)N_TOTAL * H_LAT];   // 76.8 MB
__device__ __half g_c1 [(size_t)N_TOTAL * H_LAT];   // 76.8 MB
__device__ __half g_c2 [(size_t)N_TOTAL * H_LAT];   // 76.8 MB
__device__ __half g_c3 [(size_t)N_NODES * H_LAT];   // 51.2 MB (only node rows)
__device__ int   g_counts[N_TOTAL];
__device__ int   g_row_ptr[N_TOTAL + 1];
__device__ int   g_row_fill[N_TOTAL];
__device__ int   g_bsum[256];
__device__ int2  g_csr_cv[NNZ];                     // {col, val-as-bits}

// ---------------- fp16 tensor-core GEMM: emb = X @ W_red + b_red -> g_emb (half) ----------------
#define GBM 128
#define GBN 128
#define GBK 32
#define ASTR_H 40     // halfs per A smem row (32 + 8 pad) -> ldmatrix conflict-free
#define BSTR_H 136    // halfs per B smem row (128 + 8 pad) -> ldmatrix conflict-free

__device__ __forceinline__ void ldsm_x4(unsigned& r0, unsigned& r1, unsigned& r2, unsigned& r3,
                                        unsigned addr) {
    asm volatile("ldmatrix.sync.aligned.m8n8.x4.shared.b16 {%0,%1,%2,%3}, [%4];"
                 : "=r"(r0), "=r"(r1), "=r"(r2), "=r"(r3) : "r"(addr));
}
__device__ __forceinline__ void ldsm_x4_t(unsigned& r0, unsigned& r1, unsigned& r2, unsigned& r3,
                                          unsigned addr) {
    asm volatile("ldmatrix.sync.aligned.m8n8.x4.trans.shared.b16 {%0,%1,%2,%3}, [%4];"
                 : "=r"(r0), "=r"(r1), "=r"(r2), "=r"(r3) : "r"(addr));
}

__global__ __launch_bounds__(256, 2)
void gemm_fp16_kernel(const float* __restrict__ X,
                      const float* __restrict__ W,
                      const float* __restrict__ b) {
    __shared__ __half As[GBM * ASTR_H];   // 10240 B
    __shared__ __half Bs[GBK * BSTR_H];   // 8704 B

    const int tid = threadIdx.x;
    const int warp = tid >> 5;
    const int lane = tid & 31;
    const int qid  = lane >> 2;   // lane/4
    const int qtid = lane & 3;    // lane%4

    const int block_m = blockIdx.y * GBM;
    const int block_n = blockIdx.x * GBN;
    const int wm = (warp & 3) * 32;   // warp M offset in tile
    const int wn = (warp >> 2) * 64;  // warp N offset in tile

    // gmem load mapping
    const int a_r  = tid >> 3;        // 0..31 (rows, step 32)
    const int a_c4 = (tid & 7) * 4;   // col within 32
    const int b_k  = tid >> 5;        // 0..7 (k rows, step 8)
    const int b_c4 = (tid & 31) * 4;  // col within 128

    const unsigned sA = (unsigned)__cvta_generic_to_shared(As);
    const unsigned sB = (unsigned)__cvta_generic_to_shared(Bs);

    float acc[2][8][4];
#pragma unroll
    for (int i = 0; i < 2; i++)
#pragma unroll
        for (int j = 0; j < 8; j++)
#pragma unroll
            for (int k = 0; k < 4; k++) acc[i][j][k] = 0.f;

    float4 pa[4];
    float4 pb[4];

    // prefetch tile 0
#pragma unroll
    for (int i = 0; i < 4; i++) {
        int r = block_m + a_r + i * 32;
        pa[i] = (r < N_TOTAL) ? *(const float4*)(X + (size_t)r * D_IN + a_c4)
                              : make_float4(0.f, 0.f, 0.f, 0.f);
    }
#pragma unroll
    for (int i = 0; i < 4; i++) {
        int k = b_k + i * 8;
        pb[i] = *(const float4*)(W + (size_t)k * H_LAT + block_n + b_c4);
    }

    // ldmatrix source addresses (byte offsets into shared space)
    const unsigned a_addr_base = sA + (unsigned)(((lane & 15) * ASTR_H + ((lane >> 4) << 3)) * 2);
    const unsigned b_addr_base = sB + (unsigned)((((lane & 7) + (((lane >> 3) & 1) << 3)) * BSTR_H
                                                 + wn + ((lane >> 4) << 3)) * 2);

    const int NKT = D_IN / GBK;   // 16
    for (int kt = 0; kt < NKT; kt++) {
        // store prefetched tile to smem as half
#pragma unroll
        for (int i = 0; i < 4; i++) {
            __half2* dst = (__half2*)(As + (a_r + i * 32) * ASTR_H + a_c4);
            dst[0] = __floats2half2_rn(pa[i].x, pa[i].y);
            dst[1] = __floats2half2_rn(pa[i].z, pa[i].w);
        }
#pragma unroll
        for (int i = 0; i < 4; i++) {
            __half2* dst = (__half2*)(Bs + (b_k + i * 8) * BSTR_H + b_c4);
            dst[0] = __floats2half2_rn(pb[i].x, pb[i].y);
            dst[1] = __floats2half2_rn(pb[i].z, pb[i].w);
        }
        __syncthreads();

        // prefetch next tile while computing
        if (kt + 1 < NKT) {
            int k0n = (kt + 1) * GBK;
#pragma unroll
            for (int i = 0; i < 4; i++) {
                int r = block_m + a_r + i * 32;
                pa[i] = (r < N_TOTAL) ? *(const float4*)(X + (size_t)r * D_IN + k0n + a_c4)
                                      : make_float4(0.f, 0.f, 0.f, 0.f);
            }
#pragma unroll
            for (int i = 0; i < 4; i++) {
                int k = k0n + b_k + i * 8;
                pb[i] = *(const float4*)(W + (size_t)k * H_LAT + block_n + b_c4);
            }
        }

        // compute: 2 k-steps of 16
#pragma unroll
        for (int ks = 0; ks < 2; ks++) {
            const int k0 = ks * 16;
            unsigned af[2][4], bf[4][4];
#pragma unroll
            for (int mt = 0; mt < 2; mt++) {
                unsigned addr = a_addr_base + (unsigned)(((wm + mt * 16) * ASTR_H + k0) * 2);
                ldsm_x4(af[mt][0], af[mt][1], af[mt][2], af[mt][3], addr);
            }
#pragma unroll
            for (int ng = 0; ng < 4; ng++) {
                unsigned addr = b_addr_base + (unsigned)((k0 * BSTR_H + ng * 16) * 2);
                ldsm_x4_t(bf[ng][0], bf[ng][1], bf[ng][2], bf[ng][3], addr);
            }
#pragma unroll
            for (int mt = 0; mt < 2; mt++) {
#pragma unroll
                for (int ng = 0; ng < 4; ng++) {
                    asm volatile(
                        "mma.sync.aligned.m16n8k16.row.col.f32.f16.f16.f32 "
                        "{%0,%1,%2,%3}, {%4,%5,%6,%7}, {%8,%9}, {%0,%1,%2,%3};"
                        : "+f"(acc[mt][ng * 2][0]), "+f"(acc[mt][ng * 2][1]),
                          "+f"(acc[mt][ng * 2][2]), "+f"(acc[mt][ng * 2][3])
                        : "r"(af[mt][0]), "r"(af[mt][1]), "r"(af[mt][2]), "r"(af[mt][3]),
                          "r"(bf[ng][0]), "r"(bf[ng][1]));
                    asm volatile(
                        "mma.sync.aligned.m16n8k16.row.col.f32.f16.f16.f32 "
                        "{%0,%1,%2,%3}, {%4,%5,%6,%7}, {%8,%9}, {%0,%1,%2,%3};"
                        : "+f"(acc[mt][ng * 2 + 1][0]), "+f"(acc[mt][ng * 2 + 1][1]),
                          "+f"(acc[mt][ng * 2 + 1][2]), "+f"(acc[mt][ng * 2 + 1][3])
                        : "r"(af[mt][0]), "r"(af[mt][1]), "r"(af[mt][2]), "r"(af[mt][3]),
                          "r"(bf[ng][2]), "r"(bf[ng][3]));
                }
            }
        }
        __syncthreads();
    }

    // epilogue: + bias, convert to half, store
#pragma unroll
    for (int mt = 0; mt < 2; mt++) {
        int r0 = block_m + wm + mt * 16 + qid;
#pragma unroll
        for (int nt = 0; nt < 8; nt++) {
            int c0 = block_n + wn + nt * 8 + qtid * 2;
            float bx = b[c0], by = b[c0 + 1];
            if (r0 < N_TOTAL) {
                __half2 h = __floats2half2_rn(acc[mt][nt][0] + bx, acc[mt][nt][1] + by);
                *(__half2*)(g_emb + (size_t)r0 * H_LAT + c0) = h;
            }
            if (r0 + 8 < N_TOTAL) {
                __half2 h = __floats2half2_rn(acc[mt][nt][2] + bx, acc[mt][nt][3] + by);
                *(__half2*)(g_emb + (size_t)(r0 + 8) * H_LAT + c0) = h;
            }
        }
    }
}

// ---------------- CSR build ----------------
__global__ void zero_counts_kernel() {
    int i = blockIdx.x * blockDim.x + threadIdx.x;
    if (i < N_TOTAL) g_counts[i] = 0;
}

// 4 edges per thread via int4
__global__ void hist_kernel(const int* __restrict__ rows) {
    int i = blockIdx.x * blockDim.x + threadIdx.x;
    int base = i * 4;
    if (base + 3 < NNZ) {
        int4 r4 = *(const int4*)(rows + base);
        atomicAdd(&g_counts[r4.x], 1);
        atomicAdd(&g_counts[r4.y], 1);
        atomicAdd(&g_counts[r4.z], 1);
        atomicAdd(&g_counts[r4.w], 1);
    } else {
        for (int j = base; j < NNZ; j++) atomicAdd(&g_counts[rows[j]], 1);
    }
}

#define SCAN_CHUNK 1024
#define SCAN_NBLK ((N_TOTAL + SCAN_CHUNK - 1) / SCAN_CHUNK)   // 147

__global__ void scan_pass1_kernel() {
    __shared__ int sdata[8];
    int b = blockIdx.x, t = threadIdx.x;
    int base = b * SCAN_CHUNK;
    int s = 0;
#pragma unroll
    for (int j = 0; j < 4; j++) {
        int i = base + t * 4 + j;
        if (i < N_TOTAL) s += g_counts[i];
    }
#pragma unroll
    for (int o = 16; o; o >>= 1) s += __shfl_xor_sync(0xffffffffu, s, o);
    if ((t & 31) == 0) sdata[t >> 5] = s;
    __syncthreads();
    if (t == 0) {
        int tot = 0;
        for (int w = 0; w < 8; w++) tot += sdata[w];
        g_bsum[b] = tot;
    }
}

__global__ void scan_pass2_kernel() {
    if (threadIdx.x == 0) {
        int run = 0;
        for (int i = 0; i < SCAN_NBLK; i++) {
            int v = g_bsum[i];
            g_bsum[i] = run;
            run += v;
        }
        g_row_ptr[N_TOTAL] = run;   // == NNZ
    }
}

// also writes g_row_fill (fused copy_fill)
__global__ void scan_pass3_kernel() {
    __shared__ int warp_sums[8];
    int b = blockIdx.x, t = threadIdx.x;
    int base = b * SCAN_CHUNK;
    int vals[4];
#pragma unroll
    for (int j = 0; j < 4; j++) {
        int i = base + t * 4 + j;
        vals[j] = (i < N_TOTAL) ? g_counts[i] : 0;
    }
    int tsum = vals[0] + vals[1] + vals[2] + vals[3];
    int lane = t & 31, w = t >> 5;
    int x = tsum;
#pragma unroll
    for (int o = 1; o < 32; o <<= 1) {
        int y = __shfl_up_sync(0xffffffffu, x, o);
        if (lane >= o) x += y;
    }
    if (lane == 31) warp_sums[w] = x;
    __syncthreads();
    if (t == 0) {
        int run = 0;
        for (int i = 0; i < 8; i++) {
            int v = warp_sums[i];
            warp_sums[i] = run;
            run += v;
        }
    }
    __syncthreads();
    int run = (x - tsum) + warp_sums[w] + g_bsum[b];
#pragma unroll
    for (int j = 0; j < 4; j++) {
        int i = base + t * 4 + j;
        if (i < N_TOTAL) {
            g_row_ptr[i]  = run;
            g_row_fill[i] = run;
        }
        run += vals[j];
    }
}

// 4 edges per thread via int4/float4
__global__ void scatter_kernel(const float* __restrict__ evals,
                               const int* __restrict__ rows,
                               const int* __restrict__ cols) {
    int i = blockIdx.x * blockDim.x + threadIdx.x;
    int base = i * 4;
    if (base + 3 < NNZ) {
        int4   r4 = *(const int4*)(rows + base);
        int4   c4 = *(const int4*)(cols + base);
        float4 v4 = *(const float4*)(evals + base);
        int p;
        p = atomicAdd(&g_row_fill[r4.x], 1); g_csr_cv[p] = make_int2(c4.x, __float_as_int(v4.x));
        p = atomicAdd(&g_row_fill[r4.y], 1); g_csr_cv[p] = make_int2(c4.y, __float_as_int(v4.y));
        p = atomicAdd(&g_row_fill[r4.z], 1); g_csr_cv[p] = make_int2(c4.z, __float_as_int(v4.z));
        p = atomicAdd(&g_row_fill[r4.w], 1); g_csr_cv[p] = make_int2(c4.w, __float_as_int(v4.w));
    } else {
        for (int j = base; j < NNZ; j++) {
            int r = rows[j];
            int p = atomicAdd(&g_row_fill[r], 1);
            g_csr_cv[p] = make_int2(cols[j], __float_as_int(evals[j]));
        }
    }
}

// ---------------- SpMM: next[r] = sum_e val[e]*cur[col[e]]   (half in, half out) ----------------
__device__ __forceinline__ void acc8(float* a, uint4 p, float v) {
    const __half2* h = (const __half2*)&p;
#pragma unroll
    for (int i = 0; i < 4; i++) {
        float2 f = __half22float2(h[i]);
        a[2 * i]     += v * f.x;
        a[2 * i + 1] += v * f.y;
    }
}

__global__ __launch_bounds__(256)
void spmm_half_kernel(const __half* __restrict__ cur,
                      __half* __restrict__ next,
                      int nrows) {
    int w = (blockIdx.x * blockDim.x + threadIdx.x) >> 5;
    int lane = threadIdx.x & 31;
    if (w >= nrows) return;

    int start = g_row_ptr[w];
    int end   = g_row_ptr[w + 1];

    float acc[8];
#pragma unroll
    for (int i = 0; i < 8; i++) acc[i] = 0.f;

    int e = start;
    int n4 = start + ((end - start) & ~3);
    for (; e < n4; e += 4) {
        int2 cv0 = g_csr_cv[e];
        int2 cv1 = g_csr_cv[e + 1];
        int2 cv2 = g_csr_cv[e + 2];
        int2 cv3 = g_csr_cv[e + 3];
        uint4 p0 = ((const uint4*)(cur + (size_t)cv0.x * H_LAT))[lane];
        uint4 p1 = ((const uint4*)(cur + (size_t)cv1.x * H_LAT))[lane];
        uint4 p2 = ((const uint4*)(cur + (size_t)cv2.x * H_LAT))[lane];
        uint4 p3 = ((const uint4*)(cur + (size_t)cv3.x * H_LAT))[lane];
        acc8(acc, p0, __int_as_float(cv0.y));
        acc8(acc, p1, __int_as_float(cv1.y));
        acc8(acc, p2, __int_as_float(cv2.y));
        acc8(acc, p3, __int_as_float(cv3.y));
    }
    for (; e < end; e++) {
        int2 cv0 = g_csr_cv[e];
        uint4 p0 = ((const uint4*)(cur + (size_t)cv0.x * H_LAT))[lane];
        acc8(acc, p0, __int_as_float(cv0.y));
    }

    __half2 hv[4];
#pragma unroll
    for (int i = 0; i < 4; i++)
        hv[i] = __floats2half2_rn(acc[2 * i], acc[2 * i + 1]);
    ((uint4*)(next + (size_t)w * H_LAT))[lane] = *(uint4*)hv;
}

// ---------------- classifier: out = log_softmax(((emb+c1+c2+c3)/4) @ W_cls + b_cls) ----------------
__global__ void classifier_kernel(const float* __restrict__ Wc,
                                  const float* __restrict__ bc,
                                  float* __restrict__ out) {
    __shared__ float Ws[H_LAT * N_CLASS];   // 40 KB
    __shared__ float rowbuf[4][H_LAT];      // 4 KB

    int tid = threadIdx.x;
    for (int i = tid; i < H_LAT * N_CLASS; i += 128) Ws[i] = Wc[i];
    __syncthreads();

    int warp = tid >> 5, lane = tid & 31;
    int r = blockIdx.x * 4 + warp;
    if (r >= N_NODES) return;

    size_t o = (size_t)r * H_LAT;
    uint4 pe = ((const uint4*)(g_emb + o))[lane];
    uint4 p1 = ((const uint4*)(g_c1  + o))[lane];
    uint4 p2 = ((const uint4*)(g_c2  + o))[lane];
    uint4 p3 = ((const uint4*)(g_c3  + o))[lane];
    {
        const __half2* he = (const __half2*)&pe;
        const __half2* h1 = (const __half2*)&p1;
        const __half2* h2 = (const __half2*)&p2;
        const __half2* h3 = (const __half2*)&p3;
#pragma unroll
        for (int i = 0; i < 4; i++) {
            float2 fe = __half22float2(he[i]);
            float2 f1 = __half22float2(h1[i]);
            float2 f2 = __half22float2(h2[i]);
            float2 f3 = __half22float2(h3[i]);
            rowbuf[warp][lane * 8 + 2 * i]     = (fe.x + f1.x + f2.x + f3.x) * 0.25f;
            rowbuf[warp][lane * 8 + 2 * i + 1] = (fe.y + f1.y + f2.y + f3.y) * 0.25f;
        }
    }
    __syncwarp();

    const bool has1 = (lane + 32) < N_CLASS;       // lanes 0..7
    const int  c1 = has1 ? (lane + 32) : 0;
    float z0 = bc[lane];
    float z1 = has1 ? bc[c1] : -3.0e38f;

    for (int k = 0; k < H_LAT; k++) {
        float v = rowbuf[warp][k];
        z0 += v * Ws[k * N_CLASS + lane];
        z1 += has1 ? v * Ws[k * N_CLASS + c1] : 0.f;
    }

    float m = fmaxf(z0, z1);
#pragma unroll
    for (int o2 = 16; o2; o2 >>= 1) m = fmaxf(m, __shfl_xor_sync(0xffffffffu, m, o2));
    float s = expf(z0 - m) + (has1 ? expf(z1 - m) : 0.f);
#pragma unroll
    for (int o2 = 16; o2; o2 >>= 1) s += __shfl_xor_sync(0xffffffffu, s, o2);
    float lse = m + logf(s);

    out[(size_t)r * N_CLASS + lane] = z0 - lse;
    if (has1) out[(size_t)r * N_CLASS + c1] = z1 - lse;
}

// ---------------- launch ----------------
extern "C" void kernel_launch(void* const* d_in, const int* in_sizes, int n_in,
                              void* d_out, int out_size) {
    const float* X         = (const float*)d_in[0];
    const float* W_red     = (const float*)d_in[1];
    const float* b_red     = (const float*)d_in[2];
    const float* W_cls     = (const float*)d_in[3];
    const float* b_cls     = (const float*)d_in[4];
    const float* edge_vals = (const float*)d_in[5];
    const int*   edge_rows = (const int*)d_in[6];
    const int*   edge_cols = (const int*)d_in[7];
    float* out = (float*)d_out;

    // one-time host resources (created on the pre-capture correctness call;
    // identical launch sequence every call — work is deterministic)
    static cudaStream_t s_side = nullptr;
    static cudaEvent_t  ev_fork = nullptr, ev_join = nullptr;
    if (s_side == nullptr) {
        cudaStreamCreateWithFlags(&s_side, cudaStreamNonBlocking);
        cudaEventCreateWithFlags(&ev_fork, cudaEventDisableTiming);
        cudaEventCreateWithFlags(&ev_join, cudaEventDisableTiming);
    }

    // fork: CSR build runs on side stream concurrent with GEMM on main stream
    cudaEventRecord(ev_fork, 0);
    cudaStreamWaitEvent(s_side, ev_fork, 0);

    // main stream: GEMM (fp16 tensor cores): emb -> g_emb (half)
    dim3 ggrid(H_LAT / GBN, (N_TOTAL + GBM - 1) / GBM);
    gemm_fp16_kernel<<<ggrid, 256>>>(X, W_red, b_red);

    // side stream: CSR build
    zero_counts_kernel<<<(N_TOTAL + 255) / 256, 256, 0, s_side>>>();
    hist_kernel<<<(NNZ / 4 + 255) / 256, 256, 0, s_side>>>(edge_rows);
    scan_pass1_kernel<<<SCAN_NBLK, 256, 0, s_side>>>();
    scan_pass2_kernel<<<1, 32, 0, s_side>>>();
    scan_pass3_kernel<<<SCAN_NBLK, 256, 0, s_side>>>();
    scatter_kernel<<<(NNZ / 4 + 255) / 256, 256, 0, s_side>>>(edge_vals, edge_rows, edge_cols);

    // join
    cudaEventRecord(ev_join, s_side);
    cudaStreamWaitEvent(0, ev_join, 0);

    // 3 SpMM layers (warp per row); layer 3 only needs node rows
    __half* d_emb; cudaGetSymbolAddress((void**)&d_emb, g_emb);
    __half* d_c1;  cudaGetSymbolAddress((void**)&d_c1,  g_c1);
    __half* d_c2;  cudaGetSymbolAddress((void**)&d_c2,  g_c2);
    __half* d_c3;  cudaGetSymbolAddress((void**)&d_c3,  g_c3);

    int blocks_full = (N_TOTAL * 32 + 255) / 256;
    int blocks_node = (N_NODES * 32 + 255) / 256;
    spmm_half_kernel<<<blocks_full, 256>>>(d_emb, d_c1, N_TOTAL);
    spmm_half_kernel<<<blocks_full, 256>>>(d_c1,  d_c2, N_TOTAL);
    spmm_half_kernel<<<blocks_node, 256>>>(d_c2,  d_c3, N_NODES);

    // classifier + log_softmax
    classifier_kernel<<<(N_NODES + 3) / 4, 128>>>(W_cls, b_cls, out);
}